// round 13
// baseline (speedup 1.0000x reference)
#include <cuda_runtime.h>
#include <cuda_fp16.h>
#include <stdint.h>

// Problem constants
#define B     1024
#define S     2048
#define R1    20000
#define R2    40000

#define MAIN_THREADS 512
#define NPART 3                    // part0 = rates_1st; part1,2 = rates_2nd halves
#define RPP   20000                // rates (and real entries) per partition
#define EPT   40                   // entries per thread per partition (pad 20480)
#define PART_PAD (EPT * MAIN_THREADS)   // 20480
#define ONE_IDX 2048u              // y slot holding 1.0 (first-order rb target)
#define KPAD  2048u                // pad-entry key (discarded acc slot)
#define SINK  2049                 // redirect target for non-closing stores
#define ACC_SLOTS 2050
#define Y_SLOTS 2052               // 2049 used, padded
#define CHUNK 8

// ---------------- static device scratch (no runtime allocation) ----------------
// g_counts starts zero (static zero-init); scan_kernel re-zeroes after reading.
__device__ int       g_counts[NPART][S];
__device__ int       g_cur[NPART][S];
// Key-grouped, transposed entry streams. u16x4 fields:
//   e = ra | rb<<16 | k<<32 | rid<<48   (first-order entries: rb = ONE_IDX)
__device__ uint64_t  g_et[NPART][PART_PAD];

__device__ __forceinline__ int transposeP(int pos) {
    return (pos % EPT) * MAIN_THREADS + pos / EPT;
}

__device__ __forceinline__ uint64_t pack_entry(unsigned ra, unsigned rb,
                                               unsigned k, unsigned rid) {
    return (uint64_t)ra | ((uint64_t)rb << 16) |
           ((uint64_t)k << 32) | ((uint64_t)rid << 48);
}

// ---------------- prep kernels ----------------

__global__ void hist_kernel(const int* __restrict__ inds_1p,
                            const int* __restrict__ inds_2p) {
    int i = blockIdx.x * blockDim.x + threadIdx.x;
    if (i < R1) {
        atomicAdd(&g_counts[0][inds_1p[i]], 1);
    } else if (i < R1 + R2) {
        int j = i - R1;
        atomicAdd(&g_counts[1 + (j >= RPP)][inds_2p[j]], 1);
    }
}

// One CTA per partition: exclusive scan over its 2048 bins -> running cursors.
// Re-zeroes its counts slice (restores the zero-at-entry invariant).
__global__ void scan_kernel() {
    __shared__ int buf[2][S];
    const int tid  = threadIdx.x;       // 1024 threads, 2 elems each
    const int part = blockIdx.x;

    int* cnt = g_counts[part];
    int* cur = g_cur[part];

    buf[0][tid]        = cnt[tid];
    buf[0][tid + 1024] = cnt[tid + 1024];
    cnt[tid]        = 0;
    cnt[tid + 1024] = 0;
    __syncthreads();

    int src = 0;
    for (int off = 1; off < S; off <<= 1) {
        int i0 = tid, i1 = tid + 1024;
        int v0 = buf[src][i0] + (i0 >= off ? buf[src][i0 - off] : 0);
        int v1 = buf[src][i1] + (i1 >= off ? buf[src][i1 - off] : 0);
        __syncthreads();
        buf[1 - src][i0] = v0;
        buf[1 - src][i1] = v1;
        __syncthreads();
        src ^= 1;
    }
    cur[tid]        = (tid == 0) ? 0 : buf[src][tid - 1];
    cur[tid + 1024] = buf[src][tid + 1023];
}

// Scatter entries into key-grouped transposed slots + write pad entries.
__global__ void scatter_pad_kernel(const int* __restrict__ inds_1r,
                                   const int* __restrict__ inds_1p,
                                   const int* __restrict__ inds_2r,
                                   const int* __restrict__ inds_2p) {
    int i = blockIdx.x * blockDim.x + threadIdx.x;
    if (i < R1) {
        int p   = inds_1p[i];
        int pos = atomicAdd(&g_cur[0][p], 1);
        g_et[0][transposeP(pos)] =
            pack_entry((unsigned)inds_1r[i], ONE_IDX, (unsigned)p, (unsigned)i);
    } else if (i < R1 + R2) {
        int j    = i - R1;
        int part = 1 + (j >= RPP);
        int rrel = j - (part - 1) * RPP;
        int p    = inds_2p[j];
        int pos  = atomicAdd(&g_cur[part][p], 1);
        g_et[part][transposeP(pos)] =
            pack_entry((unsigned)inds_2r[2 * j], (unsigned)inds_2r[2 * j + 1],
                       (unsigned)p, (unsigned)rrel);
    } else if (i < R1 + R2 + NPART * (PART_PAD - RPP)) {
        int q    = i - (R1 + R2);
        int part = q / (PART_PAD - RPP);
        int slot = RPP + q % (PART_PAD - RPP);
        // pad: 1.0 * 1.0 * rate[0] accumulated into discard slot KPAD
        g_et[part][transposeP(slot)] = pack_entry(ONE_IDX, ONE_IDX, KPAD, 0);
    }
}

// ---------------- main kernel ----------------
// TWO batch rows per CTA; random-read tables (y, rates) packed __half2
// {row0,row1}; fp32 register run accumulation. Unified entry format: every
// entry computes y[ra]*y[rb]*rate[rid] (first-order entries point rb at a
// 1.0 slot, making that LDS an all-lane broadcast). u16x4 fields decode in
// 4 cheap ops. Interior run closes are plain SMEM RMWs through a
// SEL-redirected address (sink for non-closes); slice-boundary runs are
// captured in registers and resolved with spread SMEM atomics after a
// barrier. Entry chunks double-buffered in registers (MLP=8).
//
// SMEM: y2h(8.2KB) + acc2(16.4KB) + rbuf2h(80KB) = 104.8KB -> 2 CTAs/SM.

#define SMEM_BYTES (Y_SLOTS * 4 + 2 * ACC_SLOTS * 4 + RPP * 4)

__device__ __forceinline__ void sweep2(
    const uint64_t* __restrict__ ep,      // g_et[part] + tid
    const __half2* __restrict__ y2h,
    const __half2* __restrict__ rbuf2h,
    float* __restrict__ acc2,
    unsigned& firstk, float& f0, float& f1, unsigned& fdone,
    unsigned& lastk, float& l0, float& l1)
{
    uint64_t buf0[CHUNK], buf1[CHUNK];
    #pragma unroll
    for (int u = 0; u < CHUNK; ++u)
        buf0[u] = ep[u * MAIN_THREADS];

    unsigned curk = 0;
    float a0 = 0.f, a1 = 0.f;
    unsigned first_done = 0;
    firstk = SINK; f0 = 0.f; f1 = 0.f;

    #pragma unroll
    for (int c = 0; c < EPT / CHUNK; ++c) {
        uint64_t* cur = (c & 1) ? buf1 : buf0;
        uint64_t* nxt = (c & 1) ? buf0 : buf1;
        if (c + 1 < EPT / CHUNK) {
            const uint64_t* np = ep + (c + 1) * CHUNK * MAIN_THREADS;
            #pragma unroll
            for (int u = 0; u < CHUNK; ++u)
                nxt[u] = np[u * MAIN_THREADS];
        }
        #pragma unroll
        for (int u = 0; u < CHUNK; ++u) {
            uint64_t e  = cur[u];
            unsigned lo = (unsigned)e;
            unsigned hi = (unsigned)(e >> 32);
            unsigned ra  = lo & 0xFFFFu;
            unsigned rb  = lo >> 16;
            unsigned k   = hi & 0xFFFFu;
            unsigned rid = hi >> 16;
            float2 fa = __half22float2(y2h[ra]);     // 1 random LDS.32
            float2 fb = __half22float2(y2h[rb]);     // random or broadcast
            float2 fr = __half22float2(rbuf2h[rid]); // 1 random LDS.32
            float v0 = fa.x * fb.x * fr.x;
            float v1 = fa.y * fb.y * fr.y;
            if (c == 0 && u == 0) {
                curk = k; a0 = v0; a1 = v1;      // prime first run
            } else {
                unsigned diff     = (k != curk) ? 1u : 0u;
                unsigned do_store = diff & first_done;
                float* addr = do_store ? (acc2 + 2 * curk) : (acc2 + 2 * SINK);
                float2 t = *(float2*)addr;        // unconditional LDS.64
                t.x += a0; t.y += a1;
                *(float2*)addr = t;               // unconditional STS.64
                unsigned cap = diff & (1u - first_done);
                firstk = cap ? curk : firstk;
                f0     = cap ? a0   : f0;
                f1     = cap ? a1   : f1;
                first_done |= diff;
                a0 = diff ? v0 : (a0 + v0);
                a1 = diff ? v1 : (a1 + v1);
                curk = k;
            }
        }
    }
    fdone = first_done;
    lastk = curk; l0 = a0; l1 = a1;
}

__global__ __launch_bounds__(MAIN_THREADS, 2)
void reaction_main_kernel(const float* __restrict__ y_in,
                          const float* __restrict__ rates_1st,
                          const float* __restrict__ rates_2nd,
                          float* __restrict__ y_out) {
    extern __shared__ char smraw[];
    __half2* y2h    = (__half2*)smraw;                        // [Y_SLOTS]
    float*   acc2   = (float*)(smraw + Y_SLOTS * 4);          // [2*ACC_SLOTS]
    __half2* rbuf2h = (__half2*)(smraw + Y_SLOTS * 4 + 2 * ACC_SLOTS * 4); // [RPP]

    const int b0  = 2 * blockIdx.x;
    const int b1  = b0 + 1;
    const int tid = threadIdx.x;

    // Load two y rows -> packed half2 (vector STS); ONE slot; zero accumulator.
    {
        const float4* s0 = (const float4*)(y_in + (size_t)b0 * S);
        const float4* s1 = (const float4*)(y_in + (size_t)b1 * S);
        float4 r0 = s0[tid], r1 = s1[tid];
        __half2 t[4];
        t[0] = __floats2half2_rn(r0.x, r1.x);
        t[1] = __floats2half2_rn(r0.y, r1.y);
        t[2] = __floats2half2_rn(r0.z, r1.z);
        t[3] = __floats2half2_rn(r0.w, r1.w);
        *(uint4*)(y2h + 4 * tid) = *(const uint4*)t;          // STS.128
        if (tid == 0)
            y2h[ONE_IDX] = __floats2half2_rn(1.f, 1.f);
        #pragma unroll
        for (int i = tid; i < 2 * ACC_SLOTS; i += MAIN_THREADS)
            acc2[i] = 0.f;
    }

    #pragma unroll 1
    for (int part = 0; part < NPART; ++part) {
        __syncthreads();   // prior sweep's rbuf reads + stores done
        {
            const float* base0 = (part == 0)
                ? rates_1st + (size_t)b0 * R1
                : rates_2nd + (size_t)b0 * R2 + (part - 1) * RPP;
            const float* base1 = (part == 0)
                ? rates_1st + (size_t)b1 * R1
                : rates_2nd + (size_t)b1 * R2 + (part - 1) * RPP;
            const float4* s0 = (const float4*)base0;
            const float4* s1 = (const float4*)base1;
            for (int i = tid; i < RPP / 4; i += MAIN_THREADS) {
                float4 r0 = __ldcs(s0 + i);
                float4 r1 = __ldcs(s1 + i);
                __half2 t[4];
                t[0] = __floats2half2_rn(r0.x, r1.x);
                t[1] = __floats2half2_rn(r0.y, r1.y);
                t[2] = __floats2half2_rn(r0.z, r1.z);
                t[3] = __floats2half2_rn(r0.w, r1.w);
                *(uint4*)(rbuf2h + 4 * i) = *(const uint4*)t;  // STS.128
            }
        }
        __syncthreads();

        unsigned firstk, fdone, lastk;
        float f0, f1, l0, l1;
        sweep2(g_et[part] + tid, y2h, rbuf2h, acc2,
               firstk, f0, f1, fdone, lastk, l0, l1);

        __syncthreads();   // interior plain stores visible before boundary atomics
        atomicAdd(&acc2[2 * lastk],     l0);
        atomicAdd(&acc2[2 * lastk + 1], l1);
        if (fdone) {
            atomicAdd(&acc2[2 * firstk],     f0);
            atomicAdd(&acc2[2 * firstk + 1], f1);
        }
    }
    __syncthreads();

    // ---- write out both rows ----
    #pragma unroll
    for (int i = tid; i < S; i += MAIN_THREADS) {
        float2 t = *(const float2*)(acc2 + 2 * i);
        y_out[(size_t)b0 * S + i] = t.x;
        y_out[(size_t)b1 * S + i] = t.y;
    }
}

// ---------------- launch ----------------

extern "C" void kernel_launch(void* const* d_in, const int* in_sizes, int n_in,
                              void* d_out, int out_size) {
    const float* y_in      = (const float*)d_in[0];
    const float* rates_1st = (const float*)d_in[1];
    const float* rates_2nd = (const float*)d_in[2];
    const int*   inds_1r   = (const int*)d_in[3];
    const int*   inds_1p   = (const int*)d_in[4];
    const int*   inds_2r   = (const int*)d_in[5];
    const int*   inds_2p   = (const int*)d_in[6];
    float*       y_out     = (float*)d_out;

    cudaFuncSetAttribute(reaction_main_kernel,
                         cudaFuncAttributeMaxDynamicSharedMemorySize,
                         SMEM_BYTES);

    // Entry-stream build (rebuilt every launch; deterministic).
    hist_kernel<<<(R1 + R2 + 255) / 256, 256>>>(inds_1p, inds_2p);
    scan_kernel<<<NPART, 1024>>>();
    int scat_n = R1 + R2 + NPART * (PART_PAD - RPP);
    scatter_pad_kernel<<<(scat_n + 255) / 256, 256>>>(inds_1r, inds_1p, inds_2r, inds_2p);

    // Main pass: one CTA per TWO batch rows
    reaction_main_kernel<<<B / 2, MAIN_THREADS, SMEM_BYTES>>>(
        y_in, rates_1st, rates_2nd, y_out);
}